// round 14
// baseline (speedup 1.0000x reference)
#include <cuda_runtime.h>
#include <cuda_fp16.h>
#include <cstdint>
#include <math.h>

// ---------------- problem constants ----------------
#define S       2048
#define HID     2048
#define NH      16
#define NKV     8
#define HD      128
#define QDIM    (NH*HD)    // 2048
#define KVDIM   (NKV*HD)   // 1024
#define KTOT    2048
#define NQKV    (QDIM + 2*KVDIM)   // 4096

// ---------------- scratch ----------------
__device__ float2 g_cs[S * 64];
__device__ __half g_Xh[S * HID];
__device__ __half g_Wqkvh[NQKV * HID];
__device__ __half g_Woh[HID * QDIM];
__device__ __half g_Qh[S * QDIM];
__device__ __half g_Kh[S * KVDIM];
__device__ __half g_Vh[S * KVDIM];
__device__ __half g_Ch[S * QDIM];

// ================= PTX helpers =================
__device__ __forceinline__ uint32_t smem_u32(const void* p) {
    uint32_t a;
    asm("{ .reg .u64 t; cvta.to.shared.u64 t, %1; cvt.u32.u64 %0, t; }" : "=r"(a) : "l"(p));
    return a;
}
__device__ __forceinline__ uint32_t h2u(__half2 h) {
    return *reinterpret_cast<uint32_t*>(&h);
}
__device__ __forceinline__ float ex2(float x) {
    float r;
    asm("ex2.approx.ftz.f32 %0, %1;" : "=f"(r) : "f"(x));
    return r;
}
__device__ __forceinline__ void cpasync16(uint32_t s, const void* g) {
    asm volatile("cp.async.cg.shared.global [%0], [%1], 16;" :: "r"(s), "l"(g));
}
__device__ __forceinline__ void ldsm4(uint32_t* r, uint32_t addr) {
    asm volatile("ldmatrix.sync.aligned.m8n8.x4.shared.b16 {%0,%1,%2,%3}, [%4];"
                 : "=r"(r[0]), "=r"(r[1]), "=r"(r[2]), "=r"(r[3]) : "r"(addr));
}
__device__ __forceinline__ void ldsm4t(uint32_t* r, uint32_t addr) {
    asm volatile("ldmatrix.sync.aligned.m8n8.x4.trans.shared.b16 {%0,%1,%2,%3}, [%4];"
                 : "=r"(r[0]), "=r"(r[1]), "=r"(r[2]), "=r"(r[3]) : "r"(addr));
}
__device__ __forceinline__ void mma16816(float* c, const uint32_t* a, const uint32_t* b) {
    asm volatile(
        "mma.sync.aligned.m16n8k16.row.col.f32.f16.f16.f32 "
        "{%0,%1,%2,%3}, {%4,%5,%6,%7}, {%8,%9}, {%0,%1,%2,%3};"
        : "+f"(c[0]), "+f"(c[1]), "+f"(c[2]), "+f"(c[3])
        : "r"(a[0]), "r"(a[1]), "r"(a[2]), "r"(a[3]), "r"(b[0]), "r"(b[1]));
}

// ============================================================
// One fused fp32 -> fp16 conversion over X + all weights
// ============================================================
#define N_X  (S * HID / 4)
#define N_WQ (QDIM * HID / 4)
#define N_WK (KVDIM * HID / 4)
#define N_WV (KVDIM * HID / 4)
#define N_WO (HID * QDIM / 4)
#define N_ALL (N_X + N_WQ + N_WK + N_WV + N_WO)

__global__ void conv_all(const float* __restrict__ X,  const float* __restrict__ wq,
                         const float* __restrict__ wk, const float* __restrict__ wv,
                         const float* __restrict__ wo,
                         __half* __restrict__ Xh, __half* __restrict__ Wqkvh,
                         __half* __restrict__ Woh) {
    int i = blockIdx.x * blockDim.x + threadIdx.x;
    if (i >= N_ALL) return;
    const float* src; __half* dst; int j;
    if (i < N_X)                       { src = X;  dst = Xh;                          j = i; }
    else if (i < N_X + N_WQ)           { src = wq; dst = Wqkvh;                       j = i - N_X; }
    else if (i < N_X + N_WQ + N_WK)    { src = wk; dst = Wqkvh + QDIM * HID;          j = i - N_X - N_WQ; }
    else if (i < N_X + N_WQ + N_WK + N_WV)
                                       { src = wv; dst = Wqkvh + (QDIM + KVDIM) * HID; j = i - N_X - N_WQ - N_WK; }
    else                               { src = wo; dst = Woh;                         j = i - N_X - N_WQ - N_WK - N_WV; }
    float4 v = ((const float4*)src)[j];
    __half2* Y = (__half2*)dst;
    Y[2 * j]     = __floats2half2_rn(v.x, v.y);
    Y[2 * j + 1] = __floats2half2_rn(v.z, v.w);
}

// ============================================================
// RoPE cos/sin table
// ============================================================
__global__ void cs_table(const int* __restrict__ pos_ids, float2* __restrict__ cs) {
    const int s = blockIdx.x;
    const int d = threadIdx.x;
    float pos = (float)pos_ids[s];
    const float NL2T_64 = 19.931568569324174f / 64.0f;
    float inv = exp2f(-(float)d * NL2T_64);
    float sn, c;
    sincosf(pos * inv, &sn, &c);
    cs[s * 64 + d] = make_float2(c, sn);
}

// ============================================================
// fp16 mma.sync GEMM mainloop (shared)
// ============================================================
#define BM 128
#define BN 128
#define BK 32
#define NIT (KTOT / BK)
#define TILEB (BM * 64)
#define STAGEB (2 * TILEB)
#define NSTAGE 4
#define GSMEM (NSTAGE * STAGEB)

__device__ __forceinline__ uint32_t swz(int row, int ci) {
    return (uint32_t)(row * 64 + ((ci ^ ((row >> 1) & 3)) << 4));
}

template <typename EpiF>
__device__ __forceinline__ void gemm_core(const __half* __restrict__ A,
                                          const __half* __restrict__ B,
                                          int m0, int bn0, char* smem, EpiF epi) {
    const uint32_t sb = smem_u32(smem);
    const int tid = threadIdx.x;
    const int lane = tid & 31;
    const int w = tid >> 5;
    const int wm = w & 1;
    const int wn = w >> 1;

    const int arow_l = (lane & 7) + ((lane >> 3) & 1) * 8;
    const int ahi_c  = lane >> 4;
    const int brow_l = (lane & 7) + ((lane >> 4) & 1) * 8;
    const int bhi_c  = (lane >> 3) & 1;
    uint32_t aoff[4], boff[2];
#pragma unroll
    for (int mi = 0; mi < 4; mi++) aoff[mi] = swz(wm * 64 + mi * 16 + arow_l, ahi_c);
#pragma unroll
    for (int nt = 0; nt < 2; nt++) boff[nt] = TILEB + swz(wn * 32 + nt * 16 + brow_l, bhi_c);

    const int grow = tid >> 2;
    const int gci  = tid & 3;

    float acc[4][4][4];
#pragma unroll
    for (int mi = 0; mi < 4; mi++)
#pragma unroll
        for (int ni = 0; ni < 4; ni++)
#pragma unroll
            for (int e = 0; e < 4; e++) acc[mi][ni][e] = 0.f;

    auto load_stage = [&](int it, int buf) {
        const int k0 = it * BK;
        const uint32_t st = sb + buf * STAGEB;
#pragma unroll
        for (int p = 0; p < 2; p++) {
            int row = grow + p * 64;
            uint32_t so = swz(row, gci);
            cpasync16(st + so,         A + (size_t)(m0 + row) * KTOT + k0 + gci * 8);
            cpasync16(st + TILEB + so, B + (size_t)(bn0 + row) * KTOT + k0 + gci * 8);
        }
    };

#pragma unroll
    for (int p = 0; p < 3; p++) {
        load_stage(p, p);
        asm volatile("cp.async.commit_group;" ::: "memory");
    }

    for (int it = 0; it < NIT; it++) {
        asm volatile("cp.async.wait_group 2;" ::: "memory");
        __syncthreads();

        const uint32_t st = sb + (it & 3) * STAGEB;
#pragma unroll
        for (int kc = 0; kc < 2; kc++) {
            const uint32_t kx = kc << 5;
            uint32_t ah[4][4], bh[4][2];
#pragma unroll
            for (int mi = 0; mi < 4; mi++) ldsm4(ah[mi], st + (aoff[mi] ^ kx));
#pragma unroll
            for (int nt = 0; nt < 2; nt++) {
                uint32_t t[4];
                ldsm4(t, st + (boff[nt] ^ kx));
                bh[2 * nt][0] = t[0]; bh[2 * nt][1] = t[1];
                bh[2 * nt + 1][0] = t[2]; bh[2 * nt + 1][1] = t[3];
            }
#pragma unroll
            for (int mi = 0; mi < 4; mi++)
#pragma unroll
                for (int ni = 0; ni < 4; ni++)
                    mma16816(acc[mi][ni], ah[mi], bh[ni]);
        }
        __syncthreads();

        if (it + 3 < NIT) load_stage(it + 3, (it + 3) & 3);
        asm volatile("cp.async.commit_group;" ::: "memory");
    }

    const int lrow = wm * 64 + (lane >> 2);
    const int lcol = wn * 32 + (lane & 3) * 2;
    epi(acc, lrow, lcol);
}

// ============================================================
// fused QKV projection + RoPE + RMS epilogue for Q/K segments.
// ============================================================
#define STR 136

__global__ __launch_bounds__(256)
void gemm_qkv(const __half* __restrict__ Xh, const __half* __restrict__ Wqkv,
              __half* __restrict__ Qh, __half* __restrict__ Kh, __half* __restrict__ Vh,
              const float* __restrict__ qnw, const float* __restrict__ knw,
              const float2* __restrict__ CS, float qscale) {
    extern __shared__ char smem[];
    const int m0 = blockIdx.y * BM;
    const int n0 = blockIdx.x * BN;

    if (n0 >= QDIM + KVDIM) {
        const int vn0 = n0 - QDIM - KVDIM;
        gemm_core(Xh, Wqkv, m0, n0, smem, [&](float a[4][4][4], int lr, int lc) {
#pragma unroll
            for (int mi = 0; mi < 4; mi++)
#pragma unroll
                for (int ni = 0; ni < 4; ni++) {
                    __half* c0 = Vh + (size_t)(m0 + lr + mi * 16) * KVDIM + vn0 + lc + ni * 8;
                    *(__half2*)c0               = __floats2half2_rn(a[mi][ni][0], a[mi][ni][1]);
                    *(__half2*)(c0 + 8 * KVDIM) = __floats2half2_rn(a[mi][ni][2], a[mi][ni][3]);
                }
        });
        return;
    }

    __half* base; int stride, nn0; const float* wv_; float osc;
    if (n0 < QDIM) { base = Qh; stride = QDIM;  nn0 = n0;        wv_ = qnw; osc = qscale; }
    else           { base = Kh; stride = KVDIM; nn0 = n0 - QDIM; wv_ = knw; osc = 1.0f;   }

    gemm_core(Xh, Wqkv, m0, n0, smem, [&](float a[4][4][4], int lr, int lc) {
        __half* stg = (__half*)smem;
        __syncthreads();
#pragma unroll
        for (int mi = 0; mi < 4; mi++)
#pragma unroll
            for (int ni = 0; ni < 4; ni++) {
                int r = lr + mi * 16;
                int c = lc + ni * 8;
                *(__half2*)&stg[r * STR + c]       = __floats2half2_rn(a[mi][ni][0], a[mi][ni][1]);
                *(__half2*)&stg[(r + 8) * STR + c] = __floats2half2_rn(a[mi][ni][2], a[mi][ni][3]);
            }
        __syncthreads();

        const int w    = threadIdx.x >> 5;
        const int lane = threadIdx.x & 31;
        float2 wa = ((const float2*)wv_)[lane];
        float2 wb = ((const float2*)wv_)[lane + 32];

#pragma unroll 4
        for (int rr = 0; rr < 16; rr++) {
            const int row = w * 16 + rr;
            const int s   = m0 + row;
            float2 cs0 = CS[s * 64 + 2 * lane];
            float2 cs1 = CS[s * 64 + 2 * lane + 1];
            float2 x1 = __half22float2(*(__half2*)&stg[row * STR + 2 * lane]);
            float2 x2 = __half22float2(*(__half2*)&stg[row * STR + 2 * lane + 64]);

            float o1x = x1.x * cs0.x - x2.x * cs0.y;
            float o1y = x1.y * cs1.x - x2.y * cs1.y;
            float o2x = x2.x * cs0.x + x1.x * cs0.y;
            float o2y = x2.y * cs1.x + x1.y * cs1.y;

            float sq = o1x * o1x + o1y * o1y + o2x * o2x + o2y * o2y;
#pragma unroll
            for (int off = 16; off; off >>= 1) sq += __shfl_xor_sync(0xffffffffu, sq, off);
            float r = rsqrtf(sq * (1.0f / 128.0f) + 1e-6f) * osc;

            __half2* y = (__half2*)(base + (size_t)s * stride + nn0);
            y[lane]      = __floats2half2_rn(o1x * r * wa.x, o1y * r * wa.y);
            y[lane + 32] = __floats2half2_rn(o2x * r * wb.x, o2y * r * wb.y);
        }
    });
}

// ---- output projection: fp32 out ----
__global__ __launch_bounds__(256)
void gemm_out(const __half* __restrict__ A, const __half* __restrict__ B,
              float* __restrict__ C) {
    extern __shared__ char smem[];
    const int m0 = blockIdx.y * BM;
    const int n0 = blockIdx.x * BN;
    gemm_core(A, B, m0, n0, smem, [&](float a[4][4][4], int lr, int lc) {
#pragma unroll
        for (int mi = 0; mi < 4; mi++)
#pragma unroll
            for (int ni = 0; ni < 4; ni++) {
                float* c0 = C + (size_t)(m0 + lr + mi * 16) * QDIM + n0 + lc + ni * 8;
                float* c1 = c0 + 8 * QDIM;
                *(float2*)c0 = make_float2(a[mi][ni][0], a[mi][ni][1]);
                *(float2*)c1 = make_float2(a[mi][ni][2], a[mi][ni][3]);
            }
    });
}

// ============================================================
// fp16 tensor-core causal GQA flash attention.
// q-tile 128 (8 warps, 16 rows each), kv-tile 64, 3-stage KV ring.
// ============================================================
#define AQT 128
#define AKT 64
#define ASM_Q 0
#define ASM_KV0 32768                        // Q = 32KB
#define ASM_TOT (32768 + 3 * 32768)          // 131072

__device__ __forceinline__ uint32_t aswz(int row, int c) {
    return (uint32_t)(row * 256 + ((c ^ (row & 7)) << 4));
}

__global__ __launch_bounds__(256)
void attn_mma(const __half* __restrict__ Qh, const __half* __restrict__ Kh,
              const __half* __restrict__ Vh, __half* __restrict__ Ch) {
    extern __shared__ char sm[];
    const uint32_t sb = smem_u32(sm);
    const int qt = (gridDim.x - 1) - blockIdx.x;    // heavy tiles first
    const int h  = blockIdx.y;
    const int kh = h >> 1;
    const int tid = threadIdx.x;
    const int lane = tid & 31;
    const int w = tid >> 5;                         // 0..7
    const int q0 = qt * AQT;
    const int ntiles = 2 * qt + 2;                  // kv tiles t = 0..2qt+1

    auto load_kv = [&](int t) {
        const int k0 = t * AKT;
        const uint32_t kb = sb + ASM_KV0 + (t % 3) * 32768;
#pragma unroll
        for (int i = 0; i < 4; i++) {
            int idx = tid + i * 256;        // 0..1023
            int row = idx >> 4;
            int c   = idx & 15;
            cpasync16(kb + aswz(row, c),
                      Kh + (size_t)(k0 + row) * KVDIM + kh * HD + c * 8);
            cpasync16(kb + 16384 + aswz(row, c),
                      Vh + (size_t)(k0 + row) * KVDIM + kh * HD + c * 8);
        }
        asm volatile("cp.async.commit_group;" ::: "memory");
    };

    // Q tile (128 x 128 fp16): 2048 cp.async of 16B
#pragma unroll
    for (int i = 0; i < 8; i++) {
        int idx = tid + i * 256;
        int row = idx >> 4;
        int c   = idx & 15;
        cpasync16(sb + ASM_Q + aswz(row, c),
                  Qh + (size_t)(q0 + row) * QDIM + h * HD + c * 8);
    }
    asm volatile("cp.async.commit_group;" ::: "memory");
    load_kv(0);
    load_kv(1);

    const int arow = (lane & 7) + ((lane >> 3) & 1) * 8;
    const int ac   = lane >> 4;
    const int brow = (lane & 7) + ((lane >> 4) & 1) * 8;
    const int bc   = (lane >> 3) & 1;
    const int vrow = (lane & 7) + ((lane >> 3) & 1) * 8;
    const int vc   = lane >> 4;
    const int r0   = lane >> 2;

    // wait for Q (kv0, kv1 stay in flight), hoist Q fragments
    asm volatile("cp.async.wait_group 2;" ::: "memory");
    __syncthreads();
    uint32_t qa[8][4];
#pragma unroll
    for (int kk = 0; kk < 8; kk++)
        ldsm4(qa[kk], sb + ASM_Q + aswz(16 * w + arow, kk * 2 + ac));

    float O[16][4];
#pragma unroll
    for (int nt = 0; nt < 16; nt++)
#pragma unroll
        for (int e = 0; e < 4; e++) O[nt][e] = 0.f;
    float m0 = -1e30f, m1 = -1e30f, lp0 = 0.f, lp1 = 0.f;

    for (int t = 0; t < ntiles; t++) {
        if (t + 1 < ntiles) { asm volatile("cp.async.wait_group 1;" ::: "memory"); }
        else                { asm volatile("cp.async.wait_group 0;" ::: "memory"); }
        __syncthreads();
        if (t + 2 < ntiles) load_kv(t + 2);

        const uint32_t kB = sb + ASM_KV0 + (t % 3) * 32768;
        const uint32_t vB = kB + 16384;

        float Sx[8][4];
#pragma unroll
        for (int nn = 0; nn < 8; nn++)
#pragma unroll
            for (int e = 0; e < 4; e++) Sx[nn][e] = 0.f;

#pragma unroll
        for (int kk = 0; kk < 8; kk++) {
#pragma unroll
            for (int nt = 0; nt < 4; nt++) {
                uint32_t b[4];
                ldsm4(b, kB + aswz(nt * 16 + brow, kk * 2 + bc));
                mma16816(Sx[2 * nt],     qa[kk], b);
                mma16816(Sx[2 * nt + 1], qa[kk], b + 2);
            }
        }

        if (t >= 2 * qt) {   // diagonal region: mask col_global > row_global
            const int kbase = t * AKT;
#pragma unroll
            for (int nn = 0; nn < 8; nn++)
#pragma unroll
                for (int e = 0; e < 4; e++) {
                    int col = kbase + nn * 8 + (lane & 3) * 2 + (e & 1);
                    int row = q0 + 16 * w + r0 + 8 * (e >> 1);
                    if (col > row) Sx[nn][e] = -1e30f;
                }
        }

        float t0 = -1e30f, t1 = -1e30f;
#pragma unroll
        for (int nn = 0; nn < 8; nn++) {
            t0 = fmaxf(t0, fmaxf(Sx[nn][0], Sx[nn][1]));
            t1 = fmaxf(t1, fmaxf(Sx[nn][2], Sx[nn][3]));
        }
        t0 = fmaxf(t0, __shfl_xor_sync(0xffffffffu, t0, 1));
        t0 = fmaxf(t0, __shfl_xor_sync(0xffffffffu, t0, 2));
        t1 = fmaxf(t1, __shfl_xor_sync(0xffffffffu, t1, 1));
        t1 = fmaxf(t1, __shfl_xor_sync(0xffffffffu, t1, 2));
        float n0 = fmaxf(m0, t0), n1 = fmaxf(m1, t1);
        float a0 = ex2(m0 - n0), a1 = ex2(m1 - n1);
        m0 = n0; m1 = n1; lp0 *= a0; lp1 *= a1;
#pragma unroll
        for (int nt = 0; nt < 16; nt++) {
            O[nt][0] *= a0; O[nt][1] *= a0; O[nt][2] *= a1; O[nt][3] *= a1;
        }

        uint32_t pa[4][4];
#pragma unroll
        for (int j = 0; j < 4; j++) {
            float p00 = ex2(Sx[2 * j][0] - n0),     p01 = ex2(Sx[2 * j][1] - n0);
            float p02 = ex2(Sx[2 * j][2] - n1),     p03 = ex2(Sx[2 * j][3] - n1);
            float p10 = ex2(Sx[2 * j + 1][0] - n0), p11 = ex2(Sx[2 * j + 1][1] - n0);
            float p12 = ex2(Sx[2 * j + 1][2] - n1), p13 = ex2(Sx[2 * j + 1][3] - n1);
            lp0 += p00 + p01 + p10 + p11;
            lp1 += p02 + p03 + p12 + p13;
            pa[j][0] = h2u(__floats2half2_rn(p00, p01));
            pa[j][1] = h2u(__floats2half2_rn(p02, p03));
            pa[j][2] = h2u(__floats2half2_rn(p10, p11));
            pa[j][3] = h2u(__floats2half2_rn(p12, p13));
        }

#pragma unroll
        for (int j = 0; j < 4; j++) {
#pragma unroll
            for (int g = 0; g < 8; g++) {
                uint32_t b[4];
                ldsm4t(b, vB + aswz(j * 16 + vrow, g * 2 + vc));
                mma16816(O[2 * g],     pa[j], b);
                mma16816(O[2 * g + 1], pa[j], b + 2);
            }
        }
    }

    lp0 += __shfl_xor_sync(0xffffffffu, lp0, 1);
    lp0 += __shfl_xor_sync(0xffffffffu, lp0, 2);
    lp1 += __shfl_xor_sync(0xffffffffu, lp1, 1);
    lp1 += __shfl_xor_sync(0xffffffffu, lp1, 2);
    float rl0 = 1.0f / lp0, rl1 = 1.0f / lp1;

    const int ro0 = q0 + 16 * w + r0;
    const int ro1 = ro0 + 8;
    const int colb = (lane & 3) * 2;
    __half2* C2 = (__half2*)Ch;
#pragma unroll
    for (int nt = 0; nt < 16; nt++) {
        int col = nt * 8 + colb;
        C2[((size_t)ro0 * QDIM + h * HD + col) >> 1] = __floats2half2_rn(O[nt][0] * rl0, O[nt][1] * rl0);
        C2[((size_t)ro1 * QDIM + h * HD + col) >> 1] = __floats2half2_rn(O[nt][2] * rl1, O[nt][3] * rl1);
    }
}

// ============================================================
// launch
// ============================================================
extern "C" void kernel_launch(void* const* d_in, const int* in_sizes, int n_in,
                              void* d_out, int out_size) {
    const float* X   = (const float*)d_in[0];
    const int*   pos = (const int*)d_in[2];
    const float* wq  = (const float*)d_in[3];
    const float* wk  = (const float*)d_in[4];
    const float* wv  = (const float*)d_in[5];
    const float* wo  = (const float*)d_in[6];
    const float* qnw = (const float*)d_in[7];
    const float* knw = (const float*)d_in[8];
    float* out = (float*)d_out;

    float2* CS;
    cudaGetSymbolAddress((void**)&CS, g_cs);

    __half *Xh, *Wqkvh, *Woh, *Qh, *Kh, *Vh, *Ch;
    cudaGetSymbolAddress((void**)&Xh,    g_Xh);
    cudaGetSymbolAddress((void**)&Wqkvh, g_Wqkvh);
    cudaGetSymbolAddress((void**)&Woh,   g_Woh);
    cudaGetSymbolAddress((void**)&Qh,    g_Qh);
    cudaGetSymbolAddress((void**)&Kh,    g_Kh);
    cudaGetSymbolAddress((void**)&Vh,    g_Vh);
    cudaGetSymbolAddress((void**)&Ch,    g_Ch);

    cudaFuncSetAttribute(gemm_qkv, cudaFuncAttributeMaxDynamicSharedMemorySize, GSMEM);
    cudaFuncSetAttribute(gemm_out, cudaFuncAttributeMaxDynamicSharedMemorySize, GSMEM);
    cudaFuncSetAttribute(attn_mma, cudaFuncAttributeMaxDynamicSharedMemorySize, ASM_TOT);

    const int T = 256;
    cs_table<<<S, 64>>>(pos, CS);
    conv_all<<<(N_ALL + T - 1) / T, T>>>(X, wq, wk, wv, wo, Xh, Wqkvh, Woh);

    const float qscale = 0.12751744f;   // log2(e)/sqrt(128)
    gemm_qkv<<<dim3(NQKV / BN, S / BM), 256, GSMEM>>>(Xh, Wqkvh, Qh, Kh, Vh,
                                                      qnw, knw, CS, qscale);

    attn_mma<<<dim3(S / AQT, NH), 256, ASM_TOT>>>(Qh, Kh, Vh, Ch);

    gemm_out<<<dim3(QDIM / BN, S / BM), 256, GSMEM>>>(Ch, Woh, out);
}

// round 15
// speedup vs baseline: 1.0541x; 1.0541x over previous
#include <cuda_runtime.h>
#include <cuda_fp16.h>
#include <cstdint>
#include <math.h>

// ---------------- problem constants ----------------
#define S       2048
#define HID     2048
#define NH      16
#define NKV     8
#define HD      128
#define QDIM    (NH*HD)    // 2048
#define KVDIM   (NKV*HD)   // 1024
#define KTOT    2048
#define NQKV    (QDIM + 2*KVDIM)   // 4096

// ---------------- scratch ----------------
__device__ float2 g_cs[S * 64];
__device__ __half g_Xh[S * HID];
__device__ __half g_Wqkvh[NQKV * HID];
__device__ __half g_Woh[HID * QDIM];
__device__ __half g_Qh[S * QDIM];
__device__ __half g_Kh[S * KVDIM];
__device__ __half g_Vh[S * KVDIM];
__device__ __half g_Ch[S * QDIM];

// ================= PTX helpers =================
__device__ __forceinline__ uint32_t smem_u32(const void* p) {
    uint32_t a;
    asm("{ .reg .u64 t; cvta.to.shared.u64 t, %1; cvt.u32.u64 %0, t; }" : "=r"(a) : "l"(p));
    return a;
}
__device__ __forceinline__ uint32_t h2u(__half2 h) {
    return *reinterpret_cast<uint32_t*>(&h);
}
__device__ __forceinline__ float ex2(float x) {
    float r;
    asm("ex2.approx.ftz.f32 %0, %1;" : "=f"(r) : "f"(x));
    return r;
}
__device__ __forceinline__ void cpasync16(uint32_t s, const void* g) {
    asm volatile("cp.async.cg.shared.global [%0], [%1], 16;" :: "r"(s), "l"(g));
}
__device__ __forceinline__ void ldsm4(uint32_t* r, uint32_t addr) {
    asm volatile("ldmatrix.sync.aligned.m8n8.x4.shared.b16 {%0,%1,%2,%3}, [%4];"
                 : "=r"(r[0]), "=r"(r[1]), "=r"(r[2]), "=r"(r[3]) : "r"(addr));
}
__device__ __forceinline__ void ldsm4t(uint32_t* r, uint32_t addr) {
    asm volatile("ldmatrix.sync.aligned.m8n8.x4.trans.shared.b16 {%0,%1,%2,%3}, [%4];"
                 : "=r"(r[0]), "=r"(r[1]), "=r"(r[2]), "=r"(r[3]) : "r"(addr));
}
__device__ __forceinline__ void mma16816(float* c, const uint32_t* a, const uint32_t* b) {
    asm volatile(
        "mma.sync.aligned.m16n8k16.row.col.f32.f16.f16.f32 "
        "{%0,%1,%2,%3}, {%4,%5,%6,%7}, {%8,%9}, {%0,%1,%2,%3};"
        : "+f"(c[0]), "+f"(c[1]), "+f"(c[2]), "+f"(c[3])
        : "r"(a[0]), "r"(a[1]), "r"(a[2]), "r"(a[3]), "r"(b[0]), "r"(b[1]));
}

// ============================================================
// One fused fp32 -> fp16 conversion over X + all weights
// ============================================================
#define N_X  (S * HID / 4)
#define N_WQ (QDIM * HID / 4)
#define N_WK (KVDIM * HID / 4)
#define N_WV (KVDIM * HID / 4)
#define N_WO (HID * QDIM / 4)
#define N_ALL (N_X + N_WQ + N_WK + N_WV + N_WO)

__global__ void conv_all(const float* __restrict__ X,  const float* __restrict__ wq,
                         const float* __restrict__ wk, const float* __restrict__ wv,
                         const float* __restrict__ wo,
                         __half* __restrict__ Xh, __half* __restrict__ Wqkvh,
                         __half* __restrict__ Woh) {
    int i = blockIdx.x * blockDim.x + threadIdx.x;
    if (i >= N_ALL) return;
    const float* src; __half* dst; int j;
    if (i < N_X)                       { src = X;  dst = Xh;                          j = i; }
    else if (i < N_X + N_WQ)           { src = wq; dst = Wqkvh;                       j = i - N_X; }
    else if (i < N_X + N_WQ + N_WK)    { src = wk; dst = Wqkvh + QDIM * HID;          j = i - N_X - N_WQ; }
    else if (i < N_X + N_WQ + N_WK + N_WV)
                                       { src = wv; dst = Wqkvh + (QDIM + KVDIM) * HID; j = i - N_X - N_WQ - N_WK; }
    else                               { src = wo; dst = Woh;                         j = i - N_X - N_WQ - N_WK - N_WV; }
    float4 v = ((const float4*)src)[j];
    __half2* Y = (__half2*)dst;
    Y[2 * j]     = __floats2half2_rn(v.x, v.y);
    Y[2 * j + 1] = __floats2half2_rn(v.z, v.w);
}

// ============================================================
// RoPE cos/sin table
// ============================================================
__global__ void cs_table(const int* __restrict__ pos_ids, float2* __restrict__ cs) {
    const int s = blockIdx.x;
    const int d = threadIdx.x;
    float pos = (float)pos_ids[s];
    const float NL2T_64 = 19.931568569324174f / 64.0f;
    float inv = exp2f(-(float)d * NL2T_64);
    float sn, c;
    sincosf(pos * inv, &sn, &c);
    cs[s * 64 + d] = make_float2(c, sn);
}

// ============================================================
// fp16 mma.sync GEMM mainloop (shared)
// ============================================================
#define BM 128
#define BN 128
#define BK 32
#define NIT (KTOT / BK)
#define TILEB (BM * 64)
#define STAGEB (2 * TILEB)
#define NSTAGE 4
#define GSMEM (NSTAGE * STAGEB)

__device__ __forceinline__ uint32_t swz(int row, int ci) {
    return (uint32_t)(row * 64 + ((ci ^ ((row >> 1) & 3)) << 4));
}

template <typename EpiF>
__device__ __forceinline__ void gemm_core(const __half* __restrict__ A,
                                          const __half* __restrict__ B,
                                          int m0, int bn0, char* smem, EpiF epi) {
    const uint32_t sb = smem_u32(smem);
    const int tid = threadIdx.x;
    const int lane = tid & 31;
    const int w = tid >> 5;
    const int wm = w & 1;
    const int wn = w >> 1;

    const int arow_l = (lane & 7) + ((lane >> 3) & 1) * 8;
    const int ahi_c  = lane >> 4;
    const int brow_l = (lane & 7) + ((lane >> 4) & 1) * 8;
    const int bhi_c  = (lane >> 3) & 1;
    uint32_t aoff[4], boff[2];
#pragma unroll
    for (int mi = 0; mi < 4; mi++) aoff[mi] = swz(wm * 64 + mi * 16 + arow_l, ahi_c);
#pragma unroll
    for (int nt = 0; nt < 2; nt++) boff[nt] = TILEB + swz(wn * 32 + nt * 16 + brow_l, bhi_c);

    const int grow = tid >> 2;
    const int gci  = tid & 3;

    float acc[4][4][4];
#pragma unroll
    for (int mi = 0; mi < 4; mi++)
#pragma unroll
        for (int ni = 0; ni < 4; ni++)
#pragma unroll
            for (int e = 0; e < 4; e++) acc[mi][ni][e] = 0.f;

    auto load_stage = [&](int it, int buf) {
        const int k0 = it * BK;
        const uint32_t st = sb + buf * STAGEB;
#pragma unroll
        for (int p = 0; p < 2; p++) {
            int row = grow + p * 64;
            uint32_t so = swz(row, gci);
            cpasync16(st + so,         A + (size_t)(m0 + row) * KTOT + k0 + gci * 8);
            cpasync16(st + TILEB + so, B + (size_t)(bn0 + row) * KTOT + k0 + gci * 8);
        }
    };

#pragma unroll
    for (int p = 0; p < 3; p++) {
        load_stage(p, p);
        asm volatile("cp.async.commit_group;" ::: "memory");
    }

    for (int it = 0; it < NIT; it++) {
        asm volatile("cp.async.wait_group 2;" ::: "memory");
        __syncthreads();

        const uint32_t st = sb + (it & 3) * STAGEB;
#pragma unroll
        for (int kc = 0; kc < 2; kc++) {
            const uint32_t kx = kc << 5;
            uint32_t ah[4][4], bh[4][2];
#pragma unroll
            for (int mi = 0; mi < 4; mi++) ldsm4(ah[mi], st + (aoff[mi] ^ kx));
#pragma unroll
            for (int nt = 0; nt < 2; nt++) {
                uint32_t t[4];
                ldsm4(t, st + (boff[nt] ^ kx));
                bh[2 * nt][0] = t[0]; bh[2 * nt][1] = t[1];
                bh[2 * nt + 1][0] = t[2]; bh[2 * nt + 1][1] = t[3];
            }
#pragma unroll
            for (int mi = 0; mi < 4; mi++)
#pragma unroll
                for (int ni = 0; ni < 4; ni++)
                    mma16816(acc[mi][ni], ah[mi], bh[ni]);
        }
        __syncthreads();

        if (it + 3 < NIT) load_stage(it + 3, (it + 3) & 3);
        asm volatile("cp.async.commit_group;" ::: "memory");
    }

    const int lrow = wm * 64 + (lane >> 2);
    const int lcol = wn * 32 + (lane & 3) * 2;
    epi(acc, lrow, lcol);
}

// ============================================================
// fused QKV projection + RoPE + RMS epilogue for Q/K segments.
// ============================================================
#define STR 136

__global__ __launch_bounds__(256)
void gemm_qkv(const __half* __restrict__ Xh, const __half* __restrict__ Wqkv,
              __half* __restrict__ Qh, __half* __restrict__ Kh, __half* __restrict__ Vh,
              const float* __restrict__ qnw, const float* __restrict__ knw,
              const float2* __restrict__ CS, float qscale) {
    extern __shared__ char smem[];
    const int m0 = blockIdx.y * BM;
    const int n0 = blockIdx.x * BN;

    if (n0 >= QDIM + KVDIM) {
        const int vn0 = n0 - QDIM - KVDIM;
        gemm_core(Xh, Wqkv, m0, n0, smem, [&](float a[4][4][4], int lr, int lc) {
#pragma unroll
            for (int mi = 0; mi < 4; mi++)
#pragma unroll
                for (int ni = 0; ni < 4; ni++) {
                    __half* c0 = Vh + (size_t)(m0 + lr + mi * 16) * KVDIM + vn0 + lc + ni * 8;
                    *(__half2*)c0               = __floats2half2_rn(a[mi][ni][0], a[mi][ni][1]);
                    *(__half2*)(c0 + 8 * KVDIM) = __floats2half2_rn(a[mi][ni][2], a[mi][ni][3]);
                }
        });
        return;
    }

    __half* base; int stride, nn0; const float* wv_; float osc;
    if (n0 < QDIM) { base = Qh; stride = QDIM;  nn0 = n0;        wv_ = qnw; osc = qscale; }
    else           { base = Kh; stride = KVDIM; nn0 = n0 - QDIM; wv_ = knw; osc = 1.0f;   }

    gemm_core(Xh, Wqkv, m0, n0, smem, [&](float a[4][4][4], int lr, int lc) {
        __half* stg = (__half*)smem;
        __syncthreads();
#pragma unroll
        for (int mi = 0; mi < 4; mi++)
#pragma unroll
            for (int ni = 0; ni < 4; ni++) {
                int r = lr + mi * 16;
                int c = lc + ni * 8;
                *(__half2*)&stg[r * STR + c]       = __floats2half2_rn(a[mi][ni][0], a[mi][ni][1]);
                *(__half2*)&stg[(r + 8) * STR + c] = __floats2half2_rn(a[mi][ni][2], a[mi][ni][3]);
            }
        __syncthreads();

        const int w    = threadIdx.x >> 5;
        const int lane = threadIdx.x & 31;
        float2 wa = ((const float2*)wv_)[lane];
        float2 wb = ((const float2*)wv_)[lane + 32];

#pragma unroll 4
        for (int rr = 0; rr < 16; rr++) {
            const int row = w * 16 + rr;
            const int s   = m0 + row;
            float2 cs0 = CS[s * 64 + 2 * lane];
            float2 cs1 = CS[s * 64 + 2 * lane + 1];
            float2 x1 = __half22float2(*(__half2*)&stg[row * STR + 2 * lane]);
            float2 x2 = __half22float2(*(__half2*)&stg[row * STR + 2 * lane + 64]);

            float o1x = x1.x * cs0.x - x2.x * cs0.y;
            float o1y = x1.y * cs1.x - x2.y * cs1.y;
            float o2x = x2.x * cs0.x + x1.x * cs0.y;
            float o2y = x2.y * cs1.x + x1.y * cs1.y;

            float sq = o1x * o1x + o1y * o1y + o2x * o2x + o2y * o2y;
#pragma unroll
            for (int off = 16; off; off >>= 1) sq += __shfl_xor_sync(0xffffffffu, sq, off);
            float r = rsqrtf(sq * (1.0f / 128.0f) + 1e-6f) * osc;

            __half2* y = (__half2*)(base + (size_t)s * stride + nn0);
            y[lane]      = __floats2half2_rn(o1x * r * wa.x, o1y * r * wa.y);
            y[lane + 32] = __floats2half2_rn(o2x * r * wb.x, o2y * r * wb.y);
        }
    });
}

// ---- output projection: fp32 out ----
__global__ __launch_bounds__(256)
void gemm_out(const __half* __restrict__ A, const __half* __restrict__ B,
              float* __restrict__ C) {
    extern __shared__ char smem[];
    const int m0 = blockIdx.y * BM;
    const int n0 = blockIdx.x * BN;
    gemm_core(A, B, m0, n0, smem, [&](float a[4][4][4], int lr, int lc) {
#pragma unroll
        for (int mi = 0; mi < 4; mi++)
#pragma unroll
            for (int ni = 0; ni < 4; ni++) {
                float* c0 = C + (size_t)(m0 + lr + mi * 16) * QDIM + n0 + lc + ni * 8;
                float* c1 = c0 + 8 * QDIM;
                *(float2*)c0 = make_float2(a[mi][ni][0], a[mi][ni][1]);
                *(float2*)c1 = make_float2(a[mi][ni][2], a[mi][ni][3]);
            }
    });
}

// ============================================================
// fp16 tensor-core causal GQA flash attention, 3-stage KV ring,
// q-tile 64 (4 warps), vote-skipped softmax rescale.
// ============================================================
#define AQT 64
#define AKT 64
#define ASM_Q 0
#define ASM_KV0 16384
#define ASM_TOT (16384 + 3 * 32768)   // 114688

__device__ __forceinline__ uint32_t aswz(int row, int c) {
    return (uint32_t)(row * 256 + ((c ^ (row & 7)) << 4));
}

__global__ __launch_bounds__(128)
void attn_mma(const __half* __restrict__ Qh, const __half* __restrict__ Kh,
              const __half* __restrict__ Vh, __half* __restrict__ Ch) {
    extern __shared__ char sm[];
    const uint32_t sb = smem_u32(sm);
    const int qt = (gridDim.x - 1) - blockIdx.x;
    const int h  = blockIdx.y;
    const int kh = h >> 1;
    const int tid = threadIdx.x;
    const int lane = tid & 31;
    const int w = tid >> 5;
    const int q0 = qt * AQT;

    auto load_kv = [&](int t) {
        const int k0 = t * AKT;
        const uint32_t kb = sb + ASM_KV0 + (t % 3) * 32768;
#pragma unroll
        for (int i = 0; i < 8; i++) {
            int idx = tid + i * 128;
            int row = idx >> 4;
            int c   = idx & 15;
            cpasync16(kb + aswz(row, c),
                      Kh + (size_t)(k0 + row) * KVDIM + kh * HD + c * 8);
            cpasync16(kb + 16384 + aswz(row, c),
                      Vh + (size_t)(k0 + row) * KVDIM + kh * HD + c * 8);
        }
        asm volatile("cp.async.commit_group;" ::: "memory");
    };

#pragma unroll
    for (int i = 0; i < 8; i++) {
        int idx = tid + i * 128;
        int row = idx >> 4;
        int c   = idx & 15;
        cpasync16(sb + ASM_Q + aswz(row, c),
                  Qh + (size_t)(q0 + row) * QDIM + h * HD + c * 8);
    }
    asm volatile("cp.async.commit_group;" ::: "memory");
    load_kv(0);
    if (qt >= 1) load_kv(1);

    const int arow = (lane & 7) + ((lane >> 3) & 1) * 8;
    const int ac   = lane >> 4;
    const int brow = (lane & 7) + ((lane >> 4) & 1) * 8;
    const int bc   = (lane >> 3) & 1;
    const int vrow = (lane & 7) + ((lane >> 3) & 1) * 8;
    const int vc   = lane >> 4;
    const int r0   = lane >> 2;

    if (qt >= 1) { asm volatile("cp.async.wait_group 2;" ::: "memory"); }
    else         { asm volatile("cp.async.wait_group 1;" ::: "memory"); }
    __syncthreads();
    uint32_t qa[8][4];
#pragma unroll
    for (int kk = 0; kk < 8; kk++)
        ldsm4(qa[kk], sb + ASM_Q + aswz(16 * w + arow, kk * 2 + ac));

    float O[16][4];
#pragma unroll
    for (int nt = 0; nt < 16; nt++)
#pragma unroll
        for (int e = 0; e < 4; e++) O[nt][e] = 0.f;
    float m0 = -1e30f, m1 = -1e30f, lp0 = 0.f, lp1 = 0.f;

    for (int t = 0; t <= qt; t++) {
        if (t < qt) { asm volatile("cp.async.wait_group 1;" ::: "memory"); }
        else        { asm volatile("cp.async.wait_group 0;" ::: "memory"); }
        __syncthreads();
        if (t + 2 <= qt) load_kv(t + 2);

        const uint32_t kB = sb + ASM_KV0 + (t % 3) * 32768;
        const uint32_t vB = kB + 16384;

        float Sx[8][4];
#pragma unroll
        for (int nn = 0; nn < 8; nn++)
#pragma unroll
            for (int e = 0; e < 4; e++) Sx[nn][e] = 0.f;

#pragma unroll
        for (int kk = 0; kk < 8; kk++) {
#pragma unroll
            for (int nt = 0; nt < 4; nt++) {
                uint32_t b[4];
                ldsm4(b, kB + aswz(nt * 16 + brow, kk * 2 + bc));
                mma16816(Sx[2 * nt],     qa[kk], b);
                mma16816(Sx[2 * nt + 1], qa[kk], b + 2);
            }
        }

        if (t == qt) {
#pragma unroll
            for (int nn = 0; nn < 8; nn++)
#pragma unroll
                for (int e = 0; e < 4; e++) {
                    int col = nn * 8 + (lane & 3) * 2 + (e & 1);
                    int row = 16 * w + r0 + 8 * (e >> 1);
                    if (col > row) Sx[nn][e] = -1e30f;
                }
        }

        float t0 = -1e30f, t1 = -1e30f;
#pragma unroll
        for (int nn = 0; nn < 8; nn++) {
            t0 = fmaxf(t0, fmaxf(Sx[nn][0], Sx[nn][1]));
            t1 = fmaxf(t1, fmaxf(Sx[nn][2], Sx[nn][3]));
        }
        t0 = fmaxf(t0, __shfl_xor_sync(0xffffffffu, t0, 1));
        t0 = fmaxf(t0, __shfl_xor_sync(0xffffffffu, t0, 2));
        t1 = fmaxf(t1, __shfl_xor_sync(0xffffffffu, t1, 1));
        t1 = fmaxf(t1, __shfl_xor_sync(0xffffffffu, t1, 2));
        float n0 = fmaxf(m0, t0), n1 = fmaxf(m1, t1);

        // vote: if no lane's running max changed, alpha == 1 exactly -> skip rescale
        bool need = !__all_sync(0xffffffffu, (n0 == m0) & (n1 == m1));
        if (need) {
            float a0 = ex2(m0 - n0), a1 = ex2(m1 - n1);
            lp0 *= a0; lp1 *= a1;
#pragma unroll
            for (int nt = 0; nt < 16; nt++) {
                O[nt][0] *= a0; O[nt][1] *= a0; O[nt][2] *= a1; O[nt][3] *= a1;
            }
        }
        m0 = n0; m1 = n1;

        uint32_t pa[4][4];
#pragma unroll
        for (int j = 0; j < 4; j++) {
            float p00 = ex2(Sx[2 * j][0] - n0),     p01 = ex2(Sx[2 * j][1] - n0);
            float p02 = ex2(Sx[2 * j][2] - n1),     p03 = ex2(Sx[2 * j][3] - n1);
            float p10 = ex2(Sx[2 * j + 1][0] - n0), p11 = ex2(Sx[2 * j + 1][1] - n0);
            float p12 = ex2(Sx[2 * j + 1][2] - n1), p13 = ex2(Sx[2 * j + 1][3] - n1);
            lp0 += p00 + p01 + p10 + p11;
            lp1 += p02 + p03 + p12 + p13;
            pa[j][0] = h2u(__floats2half2_rn(p00, p01));
            pa[j][1] = h2u(__floats2half2_rn(p02, p03));
            pa[j][2] = h2u(__floats2half2_rn(p10, p11));
            pa[j][3] = h2u(__floats2half2_rn(p12, p13));
        }

#pragma unroll
        for (int j = 0; j < 4; j++) {
#pragma unroll
            for (int g = 0; g < 8; g++) {
                uint32_t b[4];
                ldsm4t(b, vB + aswz(j * 16 + vrow, g * 2 + vc));
                mma16816(O[2 * g],     pa[j], b);
                mma16816(O[2 * g + 1], pa[j], b + 2);
            }
        }
    }

    lp0 += __shfl_xor_sync(0xffffffffu, lp0, 1);
    lp0 += __shfl_xor_sync(0xffffffffu, lp0, 2);
    lp1 += __shfl_xor_sync(0xffffffffu, lp1, 1);
    lp1 += __shfl_xor_sync(0xffffffffu, lp1, 2);
    float rl0 = 1.0f / lp0, rl1 = 1.0f / lp1;

    const int ro0 = q0 + 16 * w + r0;
    const int ro1 = ro0 + 8;
    const int colb = (lane & 3) * 2;
    __half2* C2 = (__half2*)Ch;
#pragma unroll
    for (int nt = 0; nt < 16; nt++) {
        int col = nt * 8 + colb;
        C2[((size_t)ro0 * QDIM + h * HD + col) >> 1] = __floats2half2_rn(O[nt][0] * rl0, O[nt][1] * rl0);
        C2[((size_t)ro1 * QDIM + h * HD + col) >> 1] = __floats2half2_rn(O[nt][2] * rl1, O[nt][3] * rl1);
    }
}

// ============================================================
// launch
// ============================================================
extern "C" void kernel_launch(void* const* d_in, const int* in_sizes, int n_in,
                              void* d_out, int out_size) {
    const float* X   = (const float*)d_in[0];
    const int*   pos = (const int*)d_in[2];
    const float* wq  = (const float*)d_in[3];
    const float* wk  = (const float*)d_in[4];
    const float* wv  = (const float*)d_in[5];
    const float* wo  = (const float*)d_in[6];
    const float* qnw = (const float*)d_in[7];
    const float* knw = (const float*)d_in[8];
    float* out = (float*)d_out;

    float2* CS;
    cudaGetSymbolAddress((void**)&CS, g_cs);

    __half *Xh, *Wqkvh, *Woh, *Qh, *Kh, *Vh, *Ch;
    cudaGetSymbolAddress((void**)&Xh,    g_Xh);
    cudaGetSymbolAddress((void**)&Wqkvh, g_Wqkvh);
    cudaGetSymbolAddress((void**)&Woh,   g_Woh);
    cudaGetSymbolAddress((void**)&Qh,    g_Qh);
    cudaGetSymbolAddress((void**)&Kh,    g_Kh);
    cudaGetSymbolAddress((void**)&Vh,    g_Vh);
    cudaGetSymbolAddress((void**)&Ch,    g_Ch);

    cudaFuncSetAttribute(gemm_qkv, cudaFuncAttributeMaxDynamicSharedMemorySize, GSMEM);
    cudaFuncSetAttribute(gemm_out, cudaFuncAttributeMaxDynamicSharedMemorySize, GSMEM);
    cudaFuncSetAttribute(attn_mma, cudaFuncAttributeMaxDynamicSharedMemorySize, ASM_TOT);

    const int T = 256;
    cs_table<<<S, 64>>>(pos, CS);
    conv_all<<<(N_ALL + T - 1) / T, T>>>(X, wq, wk, wv, wo, Xh, Wqkvh, Woh);

    const float qscale = 0.12751744f;   // log2(e)/sqrt(128)
    gemm_qkv<<<dim3(NQKV / BN, S / BM), 256, GSMEM>>>(Xh, Wqkvh, Qh, Kh, Vh,
                                                      qnw, knw, CS, qscale);

    attn_mma<<<dim3(S / AQT, NH), 128, ASM_TOT>>>(Qh, Kh, Vh, Ch);

    gemm_out<<<dim3(QDIM / BN, S / BM), 256, GSMEM>>>(Ch, Woh, out);
}

// round 16
// speedup vs baseline: 1.1320x; 1.0739x over previous
#include <cuda_runtime.h>
#include <cuda_fp16.h>
#include <cstdint>
#include <math.h>

// ---------------- problem constants ----------------
#define S       2048
#define HID     2048
#define NH      16
#define NKV     8
#define HD      128
#define QDIM    (NH*HD)    // 2048
#define KVDIM   (NKV*HD)   // 1024
#define KTOT    2048
#define NQKV    (QDIM + 2*KVDIM)   // 4096

// ---------------- scratch ----------------
__device__ float2 g_cs[S * 64];
__device__ __half g_Xh[S * HID];
__device__ __half g_Wqkvh[NQKV * HID];
__device__ __half g_Woh[HID * QDIM];
__device__ __half g_Qh[S * QDIM];
__device__ __half g_Kh[S * KVDIM];
__device__ __half g_Vh[S * KVDIM];
__device__ __half g_Ch[S * QDIM];

// ================= PTX helpers =================
__device__ __forceinline__ uint32_t smem_u32(const void* p) {
    uint32_t a;
    asm("{ .reg .u64 t; cvta.to.shared.u64 t, %1; cvt.u32.u64 %0, t; }" : "=r"(a) : "l"(p));
    return a;
}
__device__ __forceinline__ uint32_t h2u(__half2 h) {
    return *reinterpret_cast<uint32_t*>(&h);
}
__device__ __forceinline__ float ex2(float x) {
    float r;
    asm("ex2.approx.ftz.f32 %0, %1;" : "=f"(r) : "f"(x));
    return r;
}
__device__ __forceinline__ void cpasync16(uint32_t s, const void* g) {
    asm volatile("cp.async.cg.shared.global [%0], [%1], 16;" :: "r"(s), "l"(g));
}
__device__ __forceinline__ void ldsm4(uint32_t* r, uint32_t addr) {
    asm volatile("ldmatrix.sync.aligned.m8n8.x4.shared.b16 {%0,%1,%2,%3}, [%4];"
                 : "=r"(r[0]), "=r"(r[1]), "=r"(r[2]), "=r"(r[3]) : "r"(addr));
}
__device__ __forceinline__ void ldsm4t(uint32_t* r, uint32_t addr) {
    asm volatile("ldmatrix.sync.aligned.m8n8.x4.trans.shared.b16 {%0,%1,%2,%3}, [%4];"
                 : "=r"(r[0]), "=r"(r[1]), "=r"(r[2]), "=r"(r[3]) : "r"(addr));
}
__device__ __forceinline__ void mma16816(float* c, const uint32_t* a, const uint32_t* b) {
    asm volatile(
        "mma.sync.aligned.m16n8k16.row.col.f32.f16.f16.f32 "
        "{%0,%1,%2,%3}, {%4,%5,%6,%7}, {%8,%9}, {%0,%1,%2,%3};"
        : "+f"(c[0]), "+f"(c[1]), "+f"(c[2]), "+f"(c[3])
        : "r"(a[0]), "r"(a[1]), "r"(a[2]), "r"(a[3]), "r"(b[0]), "r"(b[1]));
}

// ============================================================
// One fused fp32 -> fp16 conversion over X + all weights
// ============================================================
#define N_X  (S * HID / 4)
#define N_WQ (QDIM * HID / 4)
#define N_WK (KVDIM * HID / 4)
#define N_WV (KVDIM * HID / 4)
#define N_WO (HID * QDIM / 4)
#define N_ALL (N_X + N_WQ + N_WK + N_WV + N_WO)

__global__ void conv_all(const float* __restrict__ X,  const float* __restrict__ wq,
                         const float* __restrict__ wk, const float* __restrict__ wv,
                         const float* __restrict__ wo,
                         __half* __restrict__ Xh, __half* __restrict__ Wqkvh,
                         __half* __restrict__ Woh) {
    int i = blockIdx.x * blockDim.x + threadIdx.x;
    if (i >= N_ALL) return;
    const float* src; __half* dst; int j;
    if (i < N_X)                       { src = X;  dst = Xh;                          j = i; }
    else if (i < N_X + N_WQ)           { src = wq; dst = Wqkvh;                       j = i - N_X; }
    else if (i < N_X + N_WQ + N_WK)    { src = wk; dst = Wqkvh + QDIM * HID;          j = i - N_X - N_WQ; }
    else if (i < N_X + N_WQ + N_WK + N_WV)
                                       { src = wv; dst = Wqkvh + (QDIM + KVDIM) * HID; j = i - N_X - N_WQ - N_WK; }
    else                               { src = wo; dst = Woh;                         j = i - N_X - N_WQ - N_WK - N_WV; }
    float4 v = ((const float4*)src)[j];
    __half2* Y = (__half2*)dst;
    Y[2 * j]     = __floats2half2_rn(v.x, v.y);
    Y[2 * j + 1] = __floats2half2_rn(v.z, v.w);
}

// ============================================================
// RoPE cos/sin table
// ============================================================
__global__ void cs_table(const int* __restrict__ pos_ids, float2* __restrict__ cs) {
    const int s = blockIdx.x;
    const int d = threadIdx.x;
    float pos = (float)pos_ids[s];
    const float NL2T_64 = 19.931568569324174f / 64.0f;
    float inv = exp2f(-(float)d * NL2T_64);
    float sn, c;
    sincosf(pos * inv, &sn, &c);
    cs[s * 64 + d] = make_float2(c, sn);
}

// ============================================================
// fp16 mma.sync GEMM mainloop: BK=64, 3-stage ring, 1 barrier/iter.
// CTA 128x128x64, 256 threads (8 warps 2m x 4n), warp tile 64x32.
// ============================================================
#define BM 128
#define BN 128
#define BK 64
#define NIT (KTOT / BK)          // 32
#define TILEB (BM * 128)         // 16KB per operand tile (128 rows x 128B)
#define STAGEB (2 * TILEB)       // 32KB
#define NSTAGE 3
#define GSMEM (NSTAGE * STAGEB)  // 96KB

// 128B rows, 8 chunks of 16B, XOR-swizzled
__device__ __forceinline__ uint32_t swz128(int row, int c) {
    return (uint32_t)(row * 128 + ((c ^ (row & 7)) << 4));
}

template <typename EpiF>
__device__ __forceinline__ void gemm_core(const __half* __restrict__ A,
                                          const __half* __restrict__ B,
                                          int m0, int bn0, char* smem, EpiF epi) {
    const uint32_t sb = smem_u32(smem);
    const int tid = threadIdx.x;
    const int lane = tid & 31;
    const int w = tid >> 5;
    const int wm = w & 1;
    const int wn = w >> 1;

    // fragment row bases + row-xor for per-kc chunk swizzle
    const int arow_l = (lane & 7) + ((lane >> 3) & 1) * 8;
    const int ahi_c  = lane >> 4;            // k-half within 16k
    const int brow_l = (lane & 7) + ((lane >> 4) & 1) * 8;
    const int bhi_c  = (lane >> 3) & 1;
    uint32_t arowb[4], browb[2];
    int arx[4], brx[2];
#pragma unroll
    for (int mi = 0; mi < 4; mi++) {
        int row = wm * 64 + mi * 16 + arow_l;
        arowb[mi] = (uint32_t)(row * 128);
        arx[mi] = row & 7;
    }
#pragma unroll
    for (int nt = 0; nt < 2; nt++) {
        int row = wn * 32 + nt * 16 + brow_l;
        browb[nt] = (uint32_t)(TILEB + row * 128);
        brx[nt] = row & 7;
    }

    // global load mapping: 1024 chunks/tile, 4 per thread per tile
    const int grow = tid >> 3;       // 0..31 (+32*i)
    const int gci  = tid & 7;

    float acc[4][4][4];
#pragma unroll
    for (int mi = 0; mi < 4; mi++)
#pragma unroll
        for (int ni = 0; ni < 4; ni++)
#pragma unroll
            for (int e = 0; e < 4; e++) acc[mi][ni][e] = 0.f;

    auto load_stage = [&](int it) {
        const int k0 = it * BK;
        const uint32_t st = sb + (it % 3) * STAGEB;
#pragma unroll
        for (int i = 0; i < 4; i++) {
            int row = grow + i * 32;
            uint32_t so = swz128(row, gci);
            cpasync16(st + so,         A + (size_t)(m0 + row) * KTOT + k0 + gci * 8);
            cpasync16(st + TILEB + so, B + (size_t)(bn0 + row) * KTOT + k0 + gci * 8);
        }
        asm volatile("cp.async.commit_group;" ::: "memory");
    };

    load_stage(0);
    load_stage(1);

    for (int it = 0; it < NIT; it++) {
        if (it + 1 < NIT) { asm volatile("cp.async.wait_group 1;" ::: "memory"); }
        else              { asm volatile("cp.async.wait_group 0;" ::: "memory"); }
        __syncthreads();
        if (it + 2 < NIT) load_stage(it + 2);

        const uint32_t st = sb + (it % 3) * STAGEB;
#pragma unroll
        for (int kc = 0; kc < 4; kc++) {
            uint32_t ah[4][4], bh[4][2];
#pragma unroll
            for (int mi = 0; mi < 4; mi++)
                ldsm4(ah[mi], st + arowb[mi] + ((uint32_t)(((2 * kc + ahi_c) ^ arx[mi]) << 4)));
#pragma unroll
            for (int nt = 0; nt < 2; nt++) {
                uint32_t t[4];
                ldsm4(t, st + browb[nt] + ((uint32_t)(((2 * kc + bhi_c) ^ brx[nt]) << 4)));
                bh[2 * nt][0] = t[0]; bh[2 * nt][1] = t[1];
                bh[2 * nt + 1][0] = t[2]; bh[2 * nt + 1][1] = t[3];
            }
#pragma unroll
            for (int mi = 0; mi < 4; mi++)
#pragma unroll
                for (int ni = 0; ni < 4; ni++)
                    mma16816(acc[mi][ni], ah[mi], bh[ni]);
        }
        // no trailing barrier: next iteration's barrier orders buffer reuse
    }

    const int lrow = wm * 64 + (lane >> 2);
    const int lcol = wn * 32 + (lane & 3) * 2;
    epi(acc, lrow, lcol);
}

// ============================================================
// fused QKV projection + RoPE + RMS epilogue for Q/K segments.
// ============================================================
#define STR 136

__global__ __launch_bounds__(256, 2)
void gemm_qkv(const __half* __restrict__ Xh, const __half* __restrict__ Wqkv,
              __half* __restrict__ Qh, __half* __restrict__ Kh, __half* __restrict__ Vh,
              const float* __restrict__ qnw, const float* __restrict__ knw,
              const float2* __restrict__ CS, float qscale) {
    extern __shared__ char smem[];
    const int m0 = blockIdx.y * BM;
    const int n0 = blockIdx.x * BN;

    if (n0 >= QDIM + KVDIM) {
        const int vn0 = n0 - QDIM - KVDIM;
        gemm_core(Xh, Wqkv, m0, n0, smem, [&](float a[4][4][4], int lr, int lc) {
#pragma unroll
            for (int mi = 0; mi < 4; mi++)
#pragma unroll
                for (int ni = 0; ni < 4; ni++) {
                    __half* c0 = Vh + (size_t)(m0 + lr + mi * 16) * KVDIM + vn0 + lc + ni * 8;
                    *(__half2*)c0               = __floats2half2_rn(a[mi][ni][0], a[mi][ni][1]);
                    *(__half2*)(c0 + 8 * KVDIM) = __floats2half2_rn(a[mi][ni][2], a[mi][ni][3]);
                }
        });
        return;
    }

    __half* base; int stride, nn0; const float* wv_; float osc;
    if (n0 < QDIM) { base = Qh; stride = QDIM;  nn0 = n0;        wv_ = qnw; osc = qscale; }
    else           { base = Kh; stride = KVDIM; nn0 = n0 - QDIM; wv_ = knw; osc = 1.0f;   }

    gemm_core(Xh, Wqkv, m0, n0, smem, [&](float a[4][4][4], int lr, int lc) {
        __half* stg = (__half*)smem;
        __syncthreads();   // mainloop smem fully consumed
#pragma unroll
        for (int mi = 0; mi < 4; mi++)
#pragma unroll
            for (int ni = 0; ni < 4; ni++) {
                int r = lr + mi * 16;
                int c = lc + ni * 8;
                *(__half2*)&stg[r * STR + c]       = __floats2half2_rn(a[mi][ni][0], a[mi][ni][1]);
                *(__half2*)&stg[(r + 8) * STR + c] = __floats2half2_rn(a[mi][ni][2], a[mi][ni][3]);
            }
        __syncthreads();

        const int w    = threadIdx.x >> 5;
        const int lane = threadIdx.x & 31;
        float2 wa = ((const float2*)wv_)[lane];
        float2 wb = ((const float2*)wv_)[lane + 32];

#pragma unroll 4
        for (int rr = 0; rr < 16; rr++) {
            const int row = w * 16 + rr;
            const int s   = m0 + row;
            float2 cs0 = CS[s * 64 + 2 * lane];
            float2 cs1 = CS[s * 64 + 2 * lane + 1];
            float2 x1 = __half22float2(*(__half2*)&stg[row * STR + 2 * lane]);
            float2 x2 = __half22float2(*(__half2*)&stg[row * STR + 2 * lane + 64]);

            float o1x = x1.x * cs0.x - x2.x * cs0.y;
            float o1y = x1.y * cs1.x - x2.y * cs1.y;
            float o2x = x2.x * cs0.x + x1.x * cs0.y;
            float o2y = x2.y * cs1.x + x1.y * cs1.y;

            float sq = o1x * o1x + o1y * o1y + o2x * o2x + o2y * o2y;
#pragma unroll
            for (int off = 16; off; off >>= 1) sq += __shfl_xor_sync(0xffffffffu, sq, off);
            float r = rsqrtf(sq * (1.0f / 128.0f) + 1e-6f) * osc;

            __half2* y = (__half2*)(base + (size_t)s * stride + nn0);
            y[lane]      = __floats2half2_rn(o1x * r * wa.x, o1y * r * wa.y);
            y[lane + 32] = __floats2half2_rn(o2x * r * wb.x, o2y * r * wb.y);
        }
    });
}

// ---- output projection: fp32 out ----
__global__ __launch_bounds__(256, 2)
void gemm_out(const __half* __restrict__ A, const __half* __restrict__ B,
              float* __restrict__ C) {
    extern __shared__ char smem[];
    const int m0 = blockIdx.y * BM;
    const int n0 = blockIdx.x * BN;
    gemm_core(A, B, m0, n0, smem, [&](float a[4][4][4], int lr, int lc) {
#pragma unroll
        for (int mi = 0; mi < 4; mi++)
#pragma unroll
            for (int ni = 0; ni < 4; ni++) {
                float* c0 = C + (size_t)(m0 + lr + mi * 16) * QDIM + n0 + lc + ni * 8;
                float* c1 = c0 + 8 * QDIM;
                *(float2*)c0 = make_float2(a[mi][ni][0], a[mi][ni][1]);
                *(float2*)c1 = make_float2(a[mi][ni][2], a[mi][ni][3]);
            }
    });
}

// ============================================================
// fp16 tensor-core causal GQA flash attention, 3-stage KV ring,
// q-tile 64 (4 warps), vote-skipped softmax rescale.
// ============================================================
#define AQT 64
#define AKT 64
#define ASM_Q 0
#define ASM_KV0 16384
#define ASM_TOT (16384 + 3 * 32768)   // 114688

__device__ __forceinline__ uint32_t aswz(int row, int c) {
    return (uint32_t)(row * 256 + ((c ^ (row & 7)) << 4));
}

__global__ __launch_bounds__(128)
void attn_mma(const __half* __restrict__ Qh, const __half* __restrict__ Kh,
              const __half* __restrict__ Vh, __half* __restrict__ Ch) {
    extern __shared__ char sm[];
    const uint32_t sb = smem_u32(sm);
    const int qt = (gridDim.x - 1) - blockIdx.x;
    const int h  = blockIdx.y;
    const int kh = h >> 1;
    const int tid = threadIdx.x;
    const int lane = tid & 31;
    const int w = tid >> 5;
    const int q0 = qt * AQT;

    auto load_kv = [&](int t) {
        const int k0 = t * AKT;
        const uint32_t kb = sb + ASM_KV0 + (t % 3) * 32768;
#pragma unroll
        for (int i = 0; i < 8; i++) {
            int idx = tid + i * 128;
            int row = idx >> 4;
            int c   = idx & 15;
            cpasync16(kb + aswz(row, c),
                      Kh + (size_t)(k0 + row) * KVDIM + kh * HD + c * 8);
            cpasync16(kb + 16384 + aswz(row, c),
                      Vh + (size_t)(k0 + row) * KVDIM + kh * HD + c * 8);
        }
        asm volatile("cp.async.commit_group;" ::: "memory");
    };

#pragma unroll
    for (int i = 0; i < 8; i++) {
        int idx = tid + i * 128;
        int row = idx >> 4;
        int c   = idx & 15;
        cpasync16(sb + ASM_Q + aswz(row, c),
                  Qh + (size_t)(q0 + row) * QDIM + h * HD + c * 8);
    }
    asm volatile("cp.async.commit_group;" ::: "memory");
    load_kv(0);
    if (qt >= 1) load_kv(1);

    const int arow = (lane & 7) + ((lane >> 3) & 1) * 8;
    const int ac   = lane >> 4;
    const int brow = (lane & 7) + ((lane >> 4) & 1) * 8;
    const int bc   = (lane >> 3) & 1;
    const int vrow = (lane & 7) + ((lane >> 3) & 1) * 8;
    const int vc   = lane >> 4;
    const int r0   = lane >> 2;

    if (qt >= 1) { asm volatile("cp.async.wait_group 2;" ::: "memory"); }
    else         { asm volatile("cp.async.wait_group 1;" ::: "memory"); }
    __syncthreads();
    uint32_t qa[8][4];
#pragma unroll
    for (int kk = 0; kk < 8; kk++)
        ldsm4(qa[kk], sb + ASM_Q + aswz(16 * w + arow, kk * 2 + ac));

    float O[16][4];
#pragma unroll
    for (int nt = 0; nt < 16; nt++)
#pragma unroll
        for (int e = 0; e < 4; e++) O[nt][e] = 0.f;
    float m0 = -1e30f, m1 = -1e30f, lp0 = 0.f, lp1 = 0.f;

    for (int t = 0; t <= qt; t++) {
        if (t < qt) { asm volatile("cp.async.wait_group 1;" ::: "memory"); }
        else        { asm volatile("cp.async.wait_group 0;" ::: "memory"); }
        __syncthreads();
        if (t + 2 <= qt) load_kv(t + 2);

        const uint32_t kB = sb + ASM_KV0 + (t % 3) * 32768;
        const uint32_t vB = kB + 16384;

        float Sx[8][4];
#pragma unroll
        for (int nn = 0; nn < 8; nn++)
#pragma unroll
            for (int e = 0; e < 4; e++) Sx[nn][e] = 0.f;

#pragma unroll
        for (int kk = 0; kk < 8; kk++) {
#pragma unroll
            for (int nt = 0; nt < 4; nt++) {
                uint32_t b[4];
                ldsm4(b, kB + aswz(nt * 16 + brow, kk * 2 + bc));
                mma16816(Sx[2 * nt],     qa[kk], b);
                mma16816(Sx[2 * nt + 1], qa[kk], b + 2);
            }
        }

        if (t == qt) {
#pragma unroll
            for (int nn = 0; nn < 8; nn++)
#pragma unroll
                for (int e = 0; e < 4; e++) {
                    int col = nn * 8 + (lane & 3) * 2 + (e & 1);
                    int row = 16 * w + r0 + 8 * (e >> 1);
                    if (col > row) Sx[nn][e] = -1e30f;
                }
        }

        float t0 = -1e30f, t1 = -1e30f;
#pragma unroll
        for (int nn = 0; nn < 8; nn++) {
            t0 = fmaxf(t0, fmaxf(Sx[nn][0], Sx[nn][1]));
            t1 = fmaxf(t1, fmaxf(Sx[nn][2], Sx[nn][3]));
        }
        t0 = fmaxf(t0, __shfl_xor_sync(0xffffffffu, t0, 1));
        t0 = fmaxf(t0, __shfl_xor_sync(0xffffffffu, t0, 2));
        t1 = fmaxf(t1, __shfl_xor_sync(0xffffffffu, t1, 1));
        t1 = fmaxf(t1, __shfl_xor_sync(0xffffffffu, t1, 2));
        float n0 = fmaxf(m0, t0), n1 = fmaxf(m1, t1);

        bool need = !__all_sync(0xffffffffu, (n0 == m0) & (n1 == m1));
        if (need) {
            float a0 = ex2(m0 - n0), a1 = ex2(m1 - n1);
            lp0 *= a0; lp1 *= a1;
#pragma unroll
            for (int nt = 0; nt < 16; nt++) {
                O[nt][0] *= a0; O[nt][1] *= a0; O[nt][2] *= a1; O[nt][3] *= a1;
            }
        }
        m0 = n0; m1 = n1;

        uint32_t pa[4][4];
#pragma unroll
        for (int j = 0; j < 4; j++) {
            float p00 = ex2(Sx[2 * j][0] - n0),     p01 = ex2(Sx[2 * j][1] - n0);
            float p02 = ex2(Sx[2 * j][2] - n1),     p03 = ex2(Sx[2 * j][3] - n1);
            float p10 = ex2(Sx[2 * j + 1][0] - n0), p11 = ex2(Sx[2 * j + 1][1] - n0);
            float p12 = ex2(Sx[2 * j + 1][2] - n1), p13 = ex2(Sx[2 * j + 1][3] - n1);
            lp0 += p00 + p01 + p10 + p11;
            lp1 += p02 + p03 + p12 + p13;
            pa[j][0] = h2u(__floats2half2_rn(p00, p01));
            pa[j][1] = h2u(__floats2half2_rn(p02, p03));
            pa[j][2] = h2u(__floats2half2_rn(p10, p11));
            pa[j][3] = h2u(__floats2half2_rn(p12, p13));
        }

#pragma unroll
        for (int j = 0; j < 4; j++) {
#pragma unroll
            for (int g = 0; g < 8; g++) {
                uint32_t b[4];
                ldsm4t(b, vB + aswz(j * 16 + vrow, g * 2 + vc));
                mma16816(O[2 * g],     pa[j], b);
                mma16816(O[2 * g + 1], pa[j], b + 2);
            }
        }
    }

    lp0 += __shfl_xor_sync(0xffffffffu, lp0, 1);
    lp0 += __shfl_xor_sync(0xffffffffu, lp0, 2);
    lp1 += __shfl_xor_sync(0xffffffffu, lp1, 1);
    lp1 += __shfl_xor_sync(0xffffffffu, lp1, 2);
    float rl0 = 1.0f / lp0, rl1 = 1.0f / lp1;

    const int ro0 = q0 + 16 * w + r0;
    const int ro1 = ro0 + 8;
    const int colb = (lane & 3) * 2;
    __half2* C2 = (__half2*)Ch;
#pragma unroll
    for (int nt = 0; nt < 16; nt++) {
        int col = nt * 8 + colb;
        C2[((size_t)ro0 * QDIM + h * HD + col) >> 1] = __floats2half2_rn(O[nt][0] * rl0, O[nt][1] * rl0);
        C2[((size_t)ro1 * QDIM + h * HD + col) >> 1] = __floats2half2_rn(O[nt][2] * rl1, O[nt][3] * rl1);
    }
}

// ============================================================
// launch
// ============================================================
extern "C" void kernel_launch(void* const* d_in, const int* in_sizes, int n_in,
                              void* d_out, int out_size) {
    const float* X   = (const float*)d_in[0];
    const int*   pos = (const int*)d_in[2];
    const float* wq  = (const float*)d_in[3];
    const float* wk  = (const float*)d_in[4];
    const float* wv  = (const float*)d_in[5];
    const float* wo  = (const float*)d_in[6];
    const float* qnw = (const float*)d_in[7];
    const float* knw = (const float*)d_in[8];
    float* out = (float*)d_out;

    float2* CS;
    cudaGetSymbolAddress((void**)&CS, g_cs);

    __half *Xh, *Wqkvh, *Woh, *Qh, *Kh, *Vh, *Ch;
    cudaGetSymbolAddress((void**)&Xh,    g_Xh);
    cudaGetSymbolAddress((void**)&Wqkvh, g_Wqkvh);
    cudaGetSymbolAddress((void**)&Woh,   g_Woh);
    cudaGetSymbolAddress((void**)&Qh,    g_Qh);
    cudaGetSymbolAddress((void**)&Kh,    g_Kh);
    cudaGetSymbolAddress((void**)&Vh,    g_Vh);
    cudaGetSymbolAddress((void**)&Ch,    g_Ch);

    cudaFuncSetAttribute(gemm_qkv, cudaFuncAttributeMaxDynamicSharedMemorySize, GSMEM);
    cudaFuncSetAttribute(gemm_out, cudaFuncAttributeMaxDynamicSharedMemorySize, GSMEM);
    cudaFuncSetAttribute(attn_mma, cudaFuncAttributeMaxDynamicSharedMemorySize, ASM_TOT);

    const int T = 256;
    cs_table<<<S, 64>>>(pos, CS);
    conv_all<<<(N_ALL + T - 1) / T, T>>>(X, wq, wk, wv, wo, Xh, Wqkvh, Woh);

    const float qscale = 0.12751744f;   // log2(e)/sqrt(128)
    gemm_qkv<<<dim3(NQKV / BN, S / BM), 256, GSMEM>>>(Xh, Wqkvh, Qh, Kh, Vh,
                                                      qnw, knw, CS, qscale);

    attn_mma<<<dim3(S / AQT, NH), 128, ASM_TOT>>>(Qh, Kh, Vh, Ch);

    gemm_out<<<dim3(QDIM / BN, S / BM), 256, GSMEM>>>(Ch, Woh, out);
}